// round 16
// baseline (speedup 1.0000x reference)
#include <cuda_runtime.h>
#include <cuda_bf16.h>
#include <cuda_fp16.h>
#include <cstdint>

// Problem dims
#define B_  2
#define S_  2048
#define D_  1024
#define H_  16
#define HD_ 64
#define GM  (B_ * S_)   // 4096
#define GN  D_          // 1024
#define GK  D_          // 1024

// softmax scale folded into Q: 1/sqrt(64) * log2(e)
#define QSCALE 0.18033688011112043f

// ---------------------------------------------------------------------------
// Scratch (__device__ globals; allocation-free rule)
// ---------------------------------------------------------------------------
__device__ __half g_x_hi[GM * GK];
__device__ __half g_x_lo[GM * GK];
__device__ __half g_qh[B_ * H_ * S_ * HD_];   // [B,H,S,HD] (Q pre-scaled, split)
__device__ __half g_ql[B_ * H_ * S_ * HD_];
__device__ __half g_kh[B_ * H_ * S_ * HD_];   // K single fp16
__device__ __half g_vh[B_ * H_ * S_ * HD_];   // V single fp16
__device__ __half g_ctx[GM * GK];             // [B,S,D] single fp16
// transposed weights [N, K] K-major, single fp16
__device__ __half g_wqt[GN * GK];
__device__ __half g_wkt[GN * GK];
__device__ __half g_wvt[GN * GK];
__device__ __half g_wot[GN * GK];

// ---------------------------------------------------------------------------
// Warp-MMA / async-copy primitives
// ---------------------------------------------------------------------------
__device__ __forceinline__ uint32_t smem_u32(const void* p) {
    uint32_t a;
    asm("{ .reg .u64 t; cvta.to.shared.u64 t, %1; cvt.u32.u64 %0, t; }"
        : "=r"(a) : "l"(p));
    return a;
}

// fp16 in, f32 acc
__device__ __forceinline__ void mma16816h(float* c, const uint32_t* a,
                                          uint32_t b0, uint32_t b1) {
    asm volatile(
        "mma.sync.aligned.m16n8k16.row.col.f32.f16.f16.f32 "
        "{%0,%1,%2,%3}, {%4,%5,%6,%7}, {%8,%9}, {%0,%1,%2,%3};"
        : "+f"(c[0]), "+f"(c[1]), "+f"(c[2]), "+f"(c[3])
        : "r"(a[0]), "r"(a[1]), "r"(a[2]), "r"(a[3]), "r"(b0), "r"(b1));
}

__device__ __forceinline__ void ldmx4(uint32_t* r, uint32_t addr) {
    asm volatile("ldmatrix.sync.aligned.m8n8.x4.shared.b16 {%0,%1,%2,%3}, [%4];"
        : "=r"(r[0]), "=r"(r[1]), "=r"(r[2]), "=r"(r[3]) : "r"(addr));
}

__device__ __forceinline__ void ldmx4t(uint32_t* r, uint32_t addr) {
    asm volatile("ldmatrix.sync.aligned.m8n8.x4.trans.shared.b16 {%0,%1,%2,%3}, [%4];"
        : "=r"(r[0]), "=r"(r[1]), "=r"(r[2]), "=r"(r[3]) : "r"(addr));
}

__device__ __forceinline__ void cpa16(uint32_t s, const void* g) {
    asm volatile("cp.async.cg.shared.global [%0], [%1], 16;"
                 :: "r"(s), "l"(g) : "memory");
}
#define CP_COMMIT() asm volatile("cp.async.commit_group;" ::: "memory")
#define CP_WAIT(n)  asm volatile("cp.async.wait_group %0;" :: "n"(n) : "memory")

__device__ __forceinline__ float ex2(float x) {
    float r;
    asm("ex2.approx.f32 %0, %1;" : "=f"(r) : "f"(x));
    return r;
}

// fp16 hi/lo pack
__device__ __forceinline__ void pack_pair_h(float x, float y, unsigned& hi, unsigned& lo) {
    __half2 h = __floats2half2_rn(x, y);
    hi = *reinterpret_cast<unsigned*>(&h);
    float xr = x - __half2float(__low2half(h));
    float yr = y - __half2float(__high2half(h));
    __half2 l = __floats2half2_rn(xr, yr);
    lo = *reinterpret_cast<unsigned*>(&l);
}
__device__ __forceinline__ unsigned pack_h2(float x, float y) {
    __half2 h = __floats2half2_rn(x, y);
    return *reinterpret_cast<unsigned*>(&h);
}

// ---------------------------------------------------------------------------
// GEMM: C[128,128] tile of A[M,K] @ B[N,K]^T, fp16 in / f32 acc.
// KC=64 chunks (16 iterations), 2-stage cp.async, 256 threads = 8 warps
// (2m x 4n), warp tile 64x32, term-major.
// MODE 0: Q proj — A = x split hi/lo (2-term), B = Wq; out fp16 hi/lo +QSCALE
// MODE 1: K/V proj (z) — A = x single (1-term), B = Wk/Wv; out fp16 single
// MODE 2: out proj — A = ctx single (1-term), B = Wo; out fp32 + bias
// ---------------------------------------------------------------------------
#define GP2 72                   // smem pitch in fp16 (144 bytes) for KC=64
#define GT2 (128 * GP2 * 2)      // one tile: 18432 bytes

template <int MODE>
__global__ __launch_bounds__(256, 2)
void mma_gemm_kernel(const float* __restrict__ bias, float* __restrict__ dout)
{
    constexpr int NT  = (MODE == 0) ? 3 : 2;  // tiles per stage
    constexpr int STG = NT * GT2;
    extern __shared__ char smem[];
    const uint32_t sbase = smem_u32(smem);

    const __half *Ah, *Al = nullptr, *Bs;
    __half *OutH = nullptr, *OutL = nullptr;
    if (MODE == 0) {
        Ah = g_x_hi; Al = g_x_lo; Bs = g_wqt; OutH = g_qh; OutL = g_ql;
    } else if (MODE == 1) {
        Ah = g_x_hi;
        if (blockIdx.z == 0) { Bs = g_wkt; OutH = g_kh; }
        else                 { Bs = g_wvt; OutH = g_vh; }
    } else {
        Ah = g_ctx; Bs = g_wot;
    }

    const int m0   = blockIdx.y * 128;
    const int n0   = blockIdx.x * 128;
    const int t    = threadIdx.x;
    const int lane = t & 31;
    const int wid  = t >> 5;
    const int wm   = wid >> 2;
    const int wn   = wid & 3;

    // KC=64 tile: 128 rows x 128B data per row; 2 threads/row, 64B each
    const int lrow = t >> 1;
    const int lhalf = (t & 1) * 64;            // byte offset within row data
    const uint32_t soff = lrow * (GP2 * 2) + lhalf;

    auto issue = [&](uint32_t sb, int c) {
        size_t goA = (size_t)(m0 + lrow) * (GK * 2) + (size_t)c * 128 + lhalf;
        size_t goB = (size_t)(n0 + lrow) * (GK * 2) + (size_t)c * 128 + lhalf;
        #pragma unroll
        for (int q = 0; q < 4; q++) {
            cpa16(sb + soff + q * 16, (const char*)Ah + goA + q * 16);
            if (MODE == 0)
                cpa16(sb + GT2 + soff + q * 16, (const char*)Al + goA + q * 16);
            cpa16(sb + (NT - 1) * GT2 + soff + q * 16, (const char*)Bs + goB + q * 16);
        }
    };

    float acc[4][4][4] = {};

    const int NC = GK / 64;                    // 16 chunks
    issue(sbase, 0);
    CP_COMMIT();

    for (int c = 0; c < NC; c++) {
        if (c + 1 < NC) {
            issue(sbase + ((c + 1) & 1) * STG, c + 1);
            CP_COMMIT();
            CP_WAIT(1);
        } else {
            CP_WAIT(0);
        }
        __syncthreads();

        const uint32_t sb  = sbase + (c & 1) * STG;
        const uint32_t uAh = sb;
        const uint32_t uAl = sb + GT2;             // MODE 0 only
        const uint32_t uB  = sb + (NT - 1) * GT2;

        #pragma unroll
        for (int ks = 0; ks < 4; ks++) {
            uint32_t a_h[4][4], a_l[4][4];
            int abyte = (wm * 64 + (lane & 15)) * (GP2 * 2) + ks * 32 + (lane >> 4) * 16;
            #pragma unroll
            for (int mt = 0; mt < 4; mt++) {
                ldmx4(a_h[mt], uAh + abyte + mt * 16 * (GP2 * 2));
                if (MODE == 0)
                    ldmx4(a_l[mt], uAl + abyte + mt * 16 * (GP2 * 2));
            }
            uint32_t b[2][4];
            #pragma unroll
            for (int j = 0; j < 2; j++) {
                int bbyte = (wn * 32 + j * 16 + ((lane >> 4) << 3) + (lane & 7)) * (GP2 * 2)
                          + ks * 32 + ((lane >> 3) & 1) * 16;
                ldmx4(b[j], uB + bbyte);
            }
            #pragma unroll
            for (int mt = 0; mt < 4; mt++)
                #pragma unroll
                for (int j = 0; j < 2; j++) {
                    mma16816h(acc[mt][2 * j],     a_h[mt], b[j][0], b[j][1]);
                    mma16816h(acc[mt][2 * j + 1], a_h[mt], b[j][2], b[j][3]);
                }
            if (MODE == 0) {
                #pragma unroll
                for (int mt = 0; mt < 4; mt++)
                    #pragma unroll
                    for (int j = 0; j < 2; j++) {
                        mma16816h(acc[mt][2 * j],     a_l[mt], b[j][0], b[j][1]);
                        mma16816h(acc[mt][2 * j + 1], a_l[mt], b[j][2], b[j][3]);
                    }
            }
        }
        __syncthreads();
    }

    // Epilogue
    #pragma unroll
    for (int mt = 0; mt < 4; mt++) {
        int mA = m0 + wm * 64 + mt * 16 + (lane >> 2);
        int mB = mA + 8;
        #pragma unroll
        for (int nt = 0; nt < 4; nt++) {
            int n = n0 + wn * 32 + nt * 8 + (lane & 3) * 2;
            float c0 = acc[mt][nt][0], c1 = acc[mt][nt][1];
            float c2 = acc[mt][nt][2], c3 = acc[mt][nt][3];
            if (MODE == 0) {
                c0 *= QSCALE; c1 *= QSCALE; c2 *= QSCALE; c3 *= QSCALE;
                int h = n >> 6, hd = n & 63;
                {
                    int b = mA >> 11, s = mA & (S_ - 1);
                    size_t o = ((size_t)((b * H_ + h) * S_) + s) * HD_ + hd;
                    unsigned ph, pl;
                    pack_pair_h(c0, c1, ph, pl);
                    *(unsigned*)&OutH[o] = ph;
                    *(unsigned*)&OutL[o] = pl;
                }
                {
                    int b = mB >> 11, s = mB & (S_ - 1);
                    size_t o = ((size_t)((b * H_ + h) * S_) + s) * HD_ + hd;
                    unsigned ph, pl;
                    pack_pair_h(c2, c3, ph, pl);
                    *(unsigned*)&OutH[o] = ph;
                    *(unsigned*)&OutL[o] = pl;
                }
            } else if (MODE == 1) {
                int h = n >> 6, hd = n & 63;
                {
                    int b = mA >> 11, s = mA & (S_ - 1);
                    size_t o = ((size_t)((b * H_ + h) * S_) + s) * HD_ + hd;
                    *(unsigned*)&OutH[o] = pack_h2(c0, c1);
                }
                {
                    int b = mB >> 11, s = mB & (S_ - 1);
                    size_t o = ((size_t)((b * H_ + h) * S_) + s) * HD_ + hd;
                    *(unsigned*)&OutH[o] = pack_h2(c2, c3);
                }
            } else {
                float b0 = bias[n], b1 = bias[n + 1];
                *(float2*)&dout[(size_t)mA * GN + n] = make_float2(c0 + b0, c1 + b1);
                *(float2*)&dout[(size_t)mB * GN + n] = make_float2(c2 + b0, c3 + b1);
            }
        }
    }
}

// ---------------------------------------------------------------------------
// Flash attention (R13, unchanged — at its roofline): 2-term fp16
// (Q split / K single; P split / V single), f32 accum, causal, 2-stage.
// grid (S/64, B*H), 128 threads = 4 warps; warp owns 16 query rows.
// ---------------------------------------------------------------------------
#define AP 72                 // smem pitch in fp16 (144 bytes)
#define AT (64 * AP * 2)      // one tile: 9216 bytes
#define ASTAGE (2 * AT)       // K, V: 18432 bytes
#define SMEM_ATTN (2 * ASTAGE)

__device__ __forceinline__ void attn_issue_kv(uint32_t sb,
    const __half* K, const __half* V, int kb, int t)
{
    const uint4* gk = (const uint4*)(K + (size_t)kb * 64 * HD_);
    const uint4* gv = (const uint4*)(V + (size_t)kb * 64 * HD_);
    #pragma unroll
    for (int p = 0; p < 4; p++) {
        int idx = t + p * 128;
        int row = idx >> 3, q = idx & 7;
        uint32_t soff = row * (AP * 2) + q * 16;
        cpa16(sb + soff,      gk + idx);
        cpa16(sb + AT + soff, gv + idx);
    }
}

__global__ __launch_bounds__(128, 2)
void attn_mma_kernel()
{
    extern __shared__ char smem[];
    const uint32_t sbase = smem_u32(smem);

    const int qb   = gridDim.x - 1 - blockIdx.x;
    const int bh   = blockIdx.y;
    const int t    = threadIdx.x;
    const int lane = t & 31;
    const int wid  = t >> 5;

    const size_t head_off = (size_t)bh * S_ * HD_;
    const __half* Qh = g_qh + head_off + (size_t)qb * 64 * HD_;
    const __half* Ql = g_ql + head_off + (size_t)qb * 64 * HD_;
    const __half* K  = g_kh + head_off;
    const __half* V  = g_vh + head_off;

    // ---- stage Q (hi,lo) into stage-1 buffers via cp.async (group 0) ----
    {
        uint32_t qsb = sbase + ASTAGE;
        #pragma unroll
        for (int p = 0; p < 4; p++) {
            int idx = t + p * 128;
            int row = idx >> 3, q = idx & 7;
            uint32_t soff = row * (AP * 2) + q * 16;
            cpa16(qsb + soff,      ((const uint4*)Qh) + idx);
            cpa16(qsb + AT + soff, ((const uint4*)Ql) + idx);
        }
        CP_COMMIT();
    }
    attn_issue_kv(sbase, K, V, 0, t);
    CP_COMMIT();

    CP_WAIT(1);
    __syncthreads();

    uint32_t aq_h[4][4], aq_l[4][4];
    {
        uint32_t uQh = sbase + ASTAGE, uQl = sbase + ASTAGE + AT;
        int qbyte = (wid * 16 + (lane & 15)) * (AP * 2) + (lane >> 4) * 16;
        #pragma unroll
        for (int kc = 0; kc < 4; kc++) {
            ldmx4(aq_h[kc], uQh + qbyte + kc * 32);
            ldmx4(aq_l[kc], uQl + qbyte + kc * 32);
        }
    }
    __syncthreads();

    float oAcc[8][4] = {};
    float m0r = -1e30f, m1r = -1e30f;
    float l0 = 0.0f, l1 = 0.0f;

    for (int kb = 0; kb <= qb; kb++) {
        if (kb < qb) {
            attn_issue_kv(sbase + ((kb + 1) & 1) * ASTAGE, K, V, kb + 1, t);
            CP_COMMIT();
            CP_WAIT(1);
        } else {
            CP_WAIT(0);
        }
        __syncthreads();

        const uint32_t sb = sbase + (kb & 1) * ASTAGE;
        const uint32_t uK = sb, uV = sb + AT;

        // ---- S = Q K^T (2-term, term-major) ----
        float sc[8][4] = {};
        #pragma unroll
        for (int kc = 0; kc < 4; kc++) {
            uint32_t b[4][4];
            #pragma unroll
            for (int j = 0; j < 4; j++) {
                int bbyte = (j * 16 + ((lane >> 4) << 3) + (lane & 7)) * (AP * 2)
                          + kc * 32 + ((lane >> 3) & 1) * 16;
                ldmx4(b[j], uK + bbyte);
            }
            #pragma unroll
            for (int j = 0; j < 4; j++) {
                mma16816h(sc[2 * j],     aq_h[kc], b[j][0], b[j][1]);
                mma16816h(sc[2 * j + 1], aq_h[kc], b[j][2], b[j][3]);
            }
            #pragma unroll
            for (int j = 0; j < 4; j++) {
                mma16816h(sc[2 * j],     aq_l[kc], b[j][0], b[j][1]);
                mma16816h(sc[2 * j + 1], aq_l[kc], b[j][2], b[j][3]);
            }
        }

        // ---- causal mask ----
        if (kb == qb) {
            int r0l = wid * 16 + (lane >> 2);
            #pragma unroll
            for (int nt = 0; nt < 8; nt++) {
                int col = nt * 8 + (lane & 3) * 2;
                if (col > r0l)         sc[nt][0] = -1e30f;
                if (col + 1 > r0l)     sc[nt][1] = -1e30f;
                if (col > r0l + 8)     sc[nt][2] = -1e30f;
                if (col + 1 > r0l + 8) sc[nt][3] = -1e30f;
            }
        }

        // ---- online softmax (base-2) ----
        float mx0 = -1e30f, mx1 = -1e30f;
        #pragma unroll
        for (int nt = 0; nt < 8; nt++) {
            mx0 = fmaxf(mx0, fmaxf(sc[nt][0], sc[nt][1]));
            mx1 = fmaxf(mx1, fmaxf(sc[nt][2], sc[nt][3]));
        }
        mx0 = fmaxf(mx0, __shfl_xor_sync(0xffffffffu, mx0, 1));
        mx0 = fmaxf(mx0, __shfl_xor_sync(0xffffffffu, mx0, 2));
        mx1 = fmaxf(mx1, __shfl_xor_sync(0xffffffffu, mx1, 1));
        mx1 = fmaxf(mx1, __shfl_xor_sync(0xffffffffu, mx1, 2));

        float mn0 = fmaxf(m0r, mx0), mn1 = fmaxf(m1r, mx1);
        float cr0 = ex2(m0r - mn0), cr1 = ex2(m1r - mn1);

        float sum0 = 0.0f, sum1 = 0.0f;
        #pragma unroll
        for (int nt = 0; nt < 8; nt++) {
            float p0 = ex2(sc[nt][0] - mn0);
            float p1 = ex2(sc[nt][1] - mn0);
            float p2 = ex2(sc[nt][2] - mn1);
            float p3 = ex2(sc[nt][3] - mn1);
            sc[nt][0] = p0; sc[nt][1] = p1; sc[nt][2] = p2; sc[nt][3] = p3;
            sum0 += p0 + p1;
            sum1 += p2 + p3;
        }
        sum0 += __shfl_xor_sync(0xffffffffu, sum0, 1);
        sum0 += __shfl_xor_sync(0xffffffffu, sum0, 2);
        sum1 += __shfl_xor_sync(0xffffffffu, sum1, 1);
        sum1 += __shfl_xor_sync(0xffffffffu, sum1, 2);

        l0 = l0 * cr0 + sum0;  m0r = mn0;
        l1 = l1 * cr1 + sum1;  m1r = mn1;

        #pragma unroll
        for (int nt = 0; nt < 8; nt++) {
            oAcc[nt][0] *= cr0; oAcc[nt][1] *= cr0;
            oAcc[nt][2] *= cr1; oAcc[nt][3] *= cr1;
        }

        // ---- O += P V (2-term: P hi/lo, V single; term-major) ----
        #pragma unroll
        for (int kc = 0; kc < 4; kc++) {
            uint32_t pa_h[4], pa_l[4];
            pack_pair_h(sc[2 * kc][0],     sc[2 * kc][1],     pa_h[0], pa_l[0]);
            pack_pair_h(sc[2 * kc][2],     sc[2 * kc][3],     pa_h[1], pa_l[1]);
            pack_pair_h(sc[2 * kc + 1][0], sc[2 * kc + 1][1], pa_h[2], pa_l[2]);
            pack_pair_h(sc[2 * kc + 1][2], sc[2 * kc + 1][3], pa_h[3], pa_l[3]);
            uint32_t v[4][4];
            #pragma unroll
            for (int j = 0; j < 4; j++) {
                int key   = kc * 16 + ((lane >> 3) & 1) * 8 + (lane & 7);
                int hd    = j * 16 + (lane >> 4) * 8;
                int vbyte = key * (AP * 2) + hd * 2;
                ldmx4t(v[j], uV + vbyte);
            }
            #pragma unroll
            for (int j = 0; j < 4; j++) {
                mma16816h(oAcc[2 * j],     pa_h, v[j][0], v[j][1]);
                mma16816h(oAcc[2 * j + 1], pa_h, v[j][2], v[j][3]);
            }
            #pragma unroll
            for (int j = 0; j < 4; j++) {
                mma16816h(oAcc[2 * j],     pa_l, v[j][0], v[j][1]);
                mma16816h(oAcc[2 * j + 1], pa_l, v[j][2], v[j][3]);
            }
        }
        __syncthreads();
    }

    // ---- finalize: ctx single fp16 [B,S,D] ----
    const float inv0 = 1.0f / l0, inv1 = 1.0f / l1;
    const int b = bh >> 4, h = bh & 15;
    const int r0 = qb * 64 + wid * 16 + (lane >> 2);
    const int r1 = r0 + 8;
    #pragma unroll
    for (int nt = 0; nt < 8; nt++) {
        int hd = nt * 8 + (lane & 3) * 2;
        float v0 = oAcc[nt][0] * inv0, v1 = oAcc[nt][1] * inv0;
        float v2 = oAcc[nt][2] * inv1, v3 = oAcc[nt][3] * inv1;
        size_t o0 = ((size_t)(b * S_ + r0)) * D_ + h * HD_ + hd;
        size_t o1 = ((size_t)(b * S_ + r1)) * D_ + h * HD_ + hd;
        *(unsigned*)&g_ctx[o0] = pack_h2(v0, v1);
        *(unsigned*)&g_ctx[o1] = pack_h2(v2, v3);
    }
}

// ---------------------------------------------------------------------------
// fp32 -> (fp16 hi, fp16 lo) split of x
// ---------------------------------------------------------------------------
__global__ void split_x_kernel(const float4* __restrict__ src)
{
    int i = blockIdx.x * blockDim.x + threadIdx.x;
    if (i >= GM * GK / 4) return;
    float4 v = src[i];
    unsigned h0, l0p, h1, l1p;
    pack_pair_h(v.x, v.y, h0, l0p);
    pack_pair_h(v.z, v.w, h1, l1p);
    ((unsigned*)g_x_hi)[i * 2]     = h0;
    ((unsigned*)g_x_hi)[i * 2 + 1] = h1;
    ((unsigned*)g_x_lo)[i * 2]     = l0p;
    ((unsigned*)g_x_lo)[i * 2 + 1] = l1p;
}

// ---------------------------------------------------------------------------
// Batched: W [K,N] fp32 -> Wt [N,K] single fp16 for all 4 weights (blockIdx.z)
// ---------------------------------------------------------------------------
__global__ void transpose_split4_kernel(const float* __restrict__ W0,
                                        const float* __restrict__ W1,
                                        const float* __restrict__ W2,
                                        const float* __restrict__ W3)
{
    __shared__ float tile[32][33];
    const float* W;
    __half* dst;
    switch (blockIdx.z) {
        case 0:  W = W0; dst = g_wqt; break;
        case 1:  W = W1; dst = g_wkt; break;
        case 2:  W = W2; dst = g_wvt; break;
        default: W = W3; dst = g_wot; break;
    }
    const int tx = threadIdx.x, ty = threadIdx.y;
    const int k0 = blockIdx.y * 32;
    const int n0 = blockIdx.x * 32;
    #pragma unroll
    for (int j = 0; j < 4; j++)
        tile[ty + j * 8][tx] = W[(size_t)(k0 + ty + j * 8) * GN + n0 + tx];
    __syncthreads();
    #pragma unroll
    for (int j = 0; j < 4; j++) {
        int n = n0 + ty + j * 8;
        int k = k0 + tx;
        dst[(size_t)n * GK + k] = __float2half_rn(tile[tx][ty + j * 8]);
    }
}

// ---------------------------------------------------------------------------
extern "C" void kernel_launch(void* const* d_in, const int* in_sizes, int n_in,
                              void* d_out, int out_size)
{
    const float* x  = (const float*)d_in[0];
    const float* Wq = (const float*)d_in[1];
    const float* Wk = (const float*)d_in[2];
    const float* Wv = (const float*)d_in[3];
    const float* Wo = (const float*)d_in[4];
    const float* bo = (const float*)d_in[5];
    float*       out = (float*)d_out;

    cudaFuncSetAttribute(mma_gemm_kernel<0>,
                         cudaFuncAttributeMaxDynamicSharedMemorySize, 2 * 3 * GT2);
    cudaFuncSetAttribute(mma_gemm_kernel<1>,
                         cudaFuncAttributeMaxDynamicSharedMemorySize, 2 * 2 * GT2);
    cudaFuncSetAttribute(mma_gemm_kernel<2>,
                         cudaFuncAttributeMaxDynamicSharedMemorySize, 2 * 2 * GT2);
    cudaFuncSetAttribute(attn_mma_kernel,
                         cudaFuncAttributeMaxDynamicSharedMemorySize, SMEM_ATTN);

    // 1) prep: split x (fp16 hi/lo), transpose weights to single fp16
    split_x_kernel<<<(GM * GK / 4 + 255) / 256, 256>>>((const float4*)x);
    transpose_split4_kernel<<<dim3(GN / 32, GK / 32, 4), dim3(32, 8)>>>(Wq, Wk, Wv, Wo);

    // 2) Q projection (2-term, KC=64) -> fp16 hi/lo, pre-scaled
    mma_gemm_kernel<0><<<dim3(GN / 128, GM / 128, 1), 256, 2 * 3 * GT2>>>(nullptr, nullptr);
    // 2b) K/V projections (1-term, KC=64) -> fp16 single
    mma_gemm_kernel<1><<<dim3(GN / 128, GM / 128, 2), 256, 2 * 2 * GT2>>>(nullptr, nullptr);

    // 3) attention (2-term fp16) -> ctx single fp16
    attn_mma_kernel<<<dim3(S_ / 64, B_ * H_), 128, SMEM_ATTN>>>();

    // 4) output projection (1-term, KC=64) + bias -> fp32 out
    mma_gemm_kernel<2><<<dim3(GN / 128, GM / 128, 1), 256, 2 * 2 * GT2>>>(bo, out);
}

// round 17
// speedup vs baseline: 1.0863x; 1.0863x over previous
#include <cuda_runtime.h>
#include <cuda_bf16.h>
#include <cuda_fp16.h>
#include <cstdint>

// Problem dims
#define B_  2
#define S_  2048
#define D_  1024
#define H_  16
#define HD_ 64
#define GM  (B_ * S_)   // 4096
#define GN  D_          // 1024
#define GK  D_          // 1024

// softmax scale folded into Q: 1/sqrt(64) * log2(e)
#define QSCALE 0.18033688011112043f

// ---------------------------------------------------------------------------
// Scratch (__device__ globals; allocation-free rule)
// ---------------------------------------------------------------------------
__device__ __half g_x_hi[GM * GK];
__device__ __half g_x_lo[GM * GK];
__device__ __half g_qh[B_ * H_ * S_ * HD_];   // [B,H,S,HD] (Q pre-scaled, split)
__device__ __half g_ql[B_ * H_ * S_ * HD_];
__device__ __half g_kh[B_ * H_ * S_ * HD_];   // K single fp16
__device__ __half g_vh[B_ * H_ * S_ * HD_];   // V single fp16
__device__ __half g_ctx[GM * GK];             // [B,S,D] single fp16
// transposed weights [N, K] K-major, single fp16
__device__ __half g_wqt[GN * GK];
__device__ __half g_wkt[GN * GK];
__device__ __half g_wvt[GN * GK];
__device__ __half g_wot[GN * GK];

// ---------------------------------------------------------------------------
// Warp-MMA / async-copy primitives
// ---------------------------------------------------------------------------
__device__ __forceinline__ uint32_t smem_u32(const void* p) {
    uint32_t a;
    asm("{ .reg .u64 t; cvta.to.shared.u64 t, %1; cvt.u32.u64 %0, t; }"
        : "=r"(a) : "l"(p));
    return a;
}

// fp16 in, f32 acc
__device__ __forceinline__ void mma16816h(float* c, const uint32_t* a,
                                          uint32_t b0, uint32_t b1) {
    asm volatile(
        "mma.sync.aligned.m16n8k16.row.col.f32.f16.f16.f32 "
        "{%0,%1,%2,%3}, {%4,%5,%6,%7}, {%8,%9}, {%0,%1,%2,%3};"
        : "+f"(c[0]), "+f"(c[1]), "+f"(c[2]), "+f"(c[3])
        : "r"(a[0]), "r"(a[1]), "r"(a[2]), "r"(a[3]), "r"(b0), "r"(b1));
}

__device__ __forceinline__ void ldmx4(uint32_t* r, uint32_t addr) {
    asm volatile("ldmatrix.sync.aligned.m8n8.x4.shared.b16 {%0,%1,%2,%3}, [%4];"
        : "=r"(r[0]), "=r"(r[1]), "=r"(r[2]), "=r"(r[3]) : "r"(addr));
}

__device__ __forceinline__ void ldmx4t(uint32_t* r, uint32_t addr) {
    asm volatile("ldmatrix.sync.aligned.m8n8.x4.trans.shared.b16 {%0,%1,%2,%3}, [%4];"
        : "=r"(r[0]), "=r"(r[1]), "=r"(r[2]), "=r"(r[3]) : "r"(addr));
}

__device__ __forceinline__ void cpa16(uint32_t s, const void* g) {
    asm volatile("cp.async.cg.shared.global [%0], [%1], 16;"
                 :: "r"(s), "l"(g) : "memory");
}
#define CP_COMMIT() asm volatile("cp.async.commit_group;" ::: "memory")
#define CP_WAIT(n)  asm volatile("cp.async.wait_group %0;" :: "n"(n) : "memory")

__device__ __forceinline__ float ex2(float x) {
    float r;
    asm("ex2.approx.f32 %0, %1;" : "=f"(r) : "f"(x));
    return r;
}

// fp16 hi/lo pack
__device__ __forceinline__ void pack_pair_h(float x, float y, unsigned& hi, unsigned& lo) {
    __half2 h = __floats2half2_rn(x, y);
    hi = *reinterpret_cast<unsigned*>(&h);
    float xr = x - __half2float(__low2half(h));
    float yr = y - __half2float(__high2half(h));
    __half2 l = __floats2half2_rn(xr, yr);
    lo = *reinterpret_cast<unsigned*>(&l);
}
__device__ __forceinline__ unsigned pack_h2(float x, float y) {
    __half2 h = __floats2half2_rn(x, y);
    return *reinterpret_cast<unsigned*>(&h);
}

// ---------------------------------------------------------------------------
// GEMM: C[128,128] tile of A[M,K] @ B[N,K]^T, fp16 in / f32 acc.
// KC=32, 3-stage cp.async (prefetch distance 2), ONE barrier per chunk.
// 256 threads = 8 warps (2m x 4n), warp tile 64x32, term-major.
// MODE 0: Q proj — A = x split hi/lo (2-term), B = Wq; out fp16 hi/lo +QSCALE
// MODE 1: K/V proj (z) — A = x single (1-term), B = Wk/Wv; out fp16 single
// MODE 2: out proj — A = ctx single (1-term), B = Wo; out fp32 + bias
// ---------------------------------------------------------------------------
#define GP 40                 // smem pitch in fp16 (80 bytes)
#define GT (128 * GP * 2)     // one tile: 10240 bytes

template <int MODE>
__global__ __launch_bounds__(256, 2)
void mma_gemm_kernel(const float* __restrict__ bias, float* __restrict__ dout)
{
    constexpr int NT  = (MODE == 0) ? 3 : 2;  // tiles per stage
    constexpr int STG = NT * GT;
    extern __shared__ char smem[];
    const uint32_t sbase = smem_u32(smem);

    const __half *Ah, *Al = nullptr, *Bs;
    __half *OutH = nullptr, *OutL = nullptr;
    if (MODE == 0) {
        Ah = g_x_hi; Al = g_x_lo; Bs = g_wqt; OutH = g_qh; OutL = g_ql;
    } else if (MODE == 1) {
        Ah = g_x_hi;
        if (blockIdx.z == 0) { Bs = g_wkt; OutH = g_kh; }
        else                 { Bs = g_wvt; OutH = g_vh; }
    } else {
        Ah = g_ctx; Bs = g_wot;
    }

    const int m0   = blockIdx.y * 128;
    const int n0   = blockIdx.x * 128;
    const int t    = threadIdx.x;
    const int lane = t & 31;
    const int wid  = t >> 5;
    const int wm   = wid >> 2;
    const int wn   = wid & 3;

    const int lrow = t >> 1, lq = (t & 1) * 2;
    const uint32_t soff = lrow * (GP * 2) + lq * 16;

    auto issue = [&](uint32_t sb, int c) {
        size_t goA = (size_t)(m0 + lrow) * (GK * 2) + (size_t)c * 64 + lq * 16;
        size_t goB = (size_t)(n0 + lrow) * (GK * 2) + (size_t)c * 64 + lq * 16;
        cpa16(sb + soff,      (const char*)Ah + goA);
        cpa16(sb + soff + 16, (const char*)Ah + goA + 16);
        if (MODE == 0) {
            cpa16(sb + GT + soff,      (const char*)Al + goA);
            cpa16(sb + GT + soff + 16, (const char*)Al + goA + 16);
        }
        cpa16(sb + (NT - 1) * GT + soff,      (const char*)Bs + goB);
        cpa16(sb + (NT - 1) * GT + soff + 16, (const char*)Bs + goB + 16);
    };

    float acc[4][4][4] = {};

    const int NC = GK / 32;                  // 32 chunks
    issue(sbase, 0);
    CP_COMMIT();
    issue(sbase + STG, 1);
    CP_COMMIT();

    for (int c = 0; c < NC; c++) {
        // wait for chunk c (leave chunk c+1 in flight if it exists)
        if (c + 1 < NC) { CP_WAIT(1); } else { CP_WAIT(0); }
        __syncthreads();   // data ready + all warps done reading stage (c+2)%3
        if (c + 2 < NC) {
            issue(sbase + ((c + 2) % 3) * STG, c + 2);
            CP_COMMIT();
        }

        const uint32_t sb  = sbase + (c % 3) * STG;
        const uint32_t uAh = sb;
        const uint32_t uAl = sb + GT;                 // MODE 0 only
        const uint32_t uB  = sb + (NT - 1) * GT;

        #pragma unroll
        for (int ks = 0; ks < 2; ks++) {
            uint32_t a_h[4][4], a_l[4][4];
            int abyte = (wm * 64 + (lane & 15)) * (GP * 2) + ks * 32 + (lane >> 4) * 16;
            #pragma unroll
            for (int mt = 0; mt < 4; mt++) {
                ldmx4(a_h[mt], uAh + abyte + mt * 16 * (GP * 2));
                if (MODE == 0)
                    ldmx4(a_l[mt], uAl + abyte + mt * 16 * (GP * 2));
            }
            uint32_t b[2][4];
            #pragma unroll
            for (int j = 0; j < 2; j++) {
                int bbyte = (wn * 32 + j * 16 + ((lane >> 4) << 3) + (lane & 7)) * (GP * 2)
                          + ks * 32 + ((lane >> 3) & 1) * 16;
                ldmx4(b[j], uB + bbyte);
            }
            #pragma unroll
            for (int mt = 0; mt < 4; mt++)
                #pragma unroll
                for (int j = 0; j < 2; j++) {
                    mma16816h(acc[mt][2 * j],     a_h[mt], b[j][0], b[j][1]);
                    mma16816h(acc[mt][2 * j + 1], a_h[mt], b[j][2], b[j][3]);
                }
            if (MODE == 0) {
                #pragma unroll
                for (int mt = 0; mt < 4; mt++)
                    #pragma unroll
                    for (int j = 0; j < 2; j++) {
                        mma16816h(acc[mt][2 * j],     a_l[mt], b[j][0], b[j][1]);
                        mma16816h(acc[mt][2 * j + 1], a_l[mt], b[j][2], b[j][3]);
                    }
            }
        }
    }

    // Epilogue
    #pragma unroll
    for (int mt = 0; mt < 4; mt++) {
        int mA = m0 + wm * 64 + mt * 16 + (lane >> 2);
        int mB = mA + 8;
        #pragma unroll
        for (int nt = 0; nt < 4; nt++) {
            int n = n0 + wn * 32 + nt * 8 + (lane & 3) * 2;
            float c0 = acc[mt][nt][0], c1 = acc[mt][nt][1];
            float c2 = acc[mt][nt][2], c3 = acc[mt][nt][3];
            if (MODE == 0) {
                c0 *= QSCALE; c1 *= QSCALE; c2 *= QSCALE; c3 *= QSCALE;
                int h = n >> 6, hd = n & 63;
                {
                    int b = mA >> 11, s = mA & (S_ - 1);
                    size_t o = ((size_t)((b * H_ + h) * S_) + s) * HD_ + hd;
                    unsigned ph, pl;
                    pack_pair_h(c0, c1, ph, pl);
                    *(unsigned*)&OutH[o] = ph;
                    *(unsigned*)&OutL[o] = pl;
                }
                {
                    int b = mB >> 11, s = mB & (S_ - 1);
                    size_t o = ((size_t)((b * H_ + h) * S_) + s) * HD_ + hd;
                    unsigned ph, pl;
                    pack_pair_h(c2, c3, ph, pl);
                    *(unsigned*)&OutH[o] = ph;
                    *(unsigned*)&OutL[o] = pl;
                }
            } else if (MODE == 1) {
                int h = n >> 6, hd = n & 63;
                {
                    int b = mA >> 11, s = mA & (S_ - 1);
                    size_t o = ((size_t)((b * H_ + h) * S_) + s) * HD_ + hd;
                    *(unsigned*)&OutH[o] = pack_h2(c0, c1);
                }
                {
                    int b = mB >> 11, s = mB & (S_ - 1);
                    size_t o = ((size_t)((b * H_ + h) * S_) + s) * HD_ + hd;
                    *(unsigned*)&OutH[o] = pack_h2(c2, c3);
                }
            } else {
                float b0 = bias[n], b1 = bias[n + 1];
                *(float2*)&dout[(size_t)mA * GN + n] = make_float2(c0 + b0, c1 + b1);
                *(float2*)&dout[(size_t)mB * GN + n] = make_float2(c2 + b0, c3 + b1);
            }
        }
    }
}

// ---------------------------------------------------------------------------
// Flash attention (R13, unchanged — at its roofline): 2-term fp16
// (Q split / K single; P split / V single), f32 accum, causal, 2-stage.
// grid (S/64, B*H), 128 threads = 4 warps; warp owns 16 query rows.
// ---------------------------------------------------------------------------
#define AP 72                 // smem pitch in fp16 (144 bytes)
#define AT (64 * AP * 2)      // one tile: 9216 bytes
#define ASTAGE (2 * AT)       // K, V: 18432 bytes
#define SMEM_ATTN (2 * ASTAGE)

__device__ __forceinline__ void attn_issue_kv(uint32_t sb,
    const __half* K, const __half* V, int kb, int t)
{
    const uint4* gk = (const uint4*)(K + (size_t)kb * 64 * HD_);
    const uint4* gv = (const uint4*)(V + (size_t)kb * 64 * HD_);
    #pragma unroll
    for (int p = 0; p < 4; p++) {
        int idx = t + p * 128;
        int row = idx >> 3, q = idx & 7;
        uint32_t soff = row * (AP * 2) + q * 16;
        cpa16(sb + soff,      gk + idx);
        cpa16(sb + AT + soff, gv + idx);
    }
}

__global__ __launch_bounds__(128, 2)
void attn_mma_kernel()
{
    extern __shared__ char smem[];
    const uint32_t sbase = smem_u32(smem);

    const int qb   = gridDim.x - 1 - blockIdx.x;
    const int bh   = blockIdx.y;
    const int t    = threadIdx.x;
    const int lane = t & 31;
    const int wid  = t >> 5;

    const size_t head_off = (size_t)bh * S_ * HD_;
    const __half* Qh = g_qh + head_off + (size_t)qb * 64 * HD_;
    const __half* Ql = g_ql + head_off + (size_t)qb * 64 * HD_;
    const __half* K  = g_kh + head_off;
    const __half* V  = g_vh + head_off;

    // ---- stage Q (hi,lo) into stage-1 buffers via cp.async (group 0) ----
    {
        uint32_t qsb = sbase + ASTAGE;
        #pragma unroll
        for (int p = 0; p < 4; p++) {
            int idx = t + p * 128;
            int row = idx >> 3, q = idx & 7;
            uint32_t soff = row * (AP * 2) + q * 16;
            cpa16(qsb + soff,      ((const uint4*)Qh) + idx);
            cpa16(qsb + AT + soff, ((const uint4*)Ql) + idx);
        }
        CP_COMMIT();
    }
    attn_issue_kv(sbase, K, V, 0, t);
    CP_COMMIT();

    CP_WAIT(1);
    __syncthreads();

    uint32_t aq_h[4][4], aq_l[4][4];
    {
        uint32_t uQh = sbase + ASTAGE, uQl = sbase + ASTAGE + AT;
        int qbyte = (wid * 16 + (lane & 15)) * (AP * 2) + (lane >> 4) * 16;
        #pragma unroll
        for (int kc = 0; kc < 4; kc++) {
            ldmx4(aq_h[kc], uQh + qbyte + kc * 32);
            ldmx4(aq_l[kc], uQl + qbyte + kc * 32);
        }
    }
    __syncthreads();

    float oAcc[8][4] = {};
    float m0r = -1e30f, m1r = -1e30f;
    float l0 = 0.0f, l1 = 0.0f;

    for (int kb = 0; kb <= qb; kb++) {
        if (kb < qb) {
            attn_issue_kv(sbase + ((kb + 1) & 1) * ASTAGE, K, V, kb + 1, t);
            CP_COMMIT();
            CP_WAIT(1);
        } else {
            CP_WAIT(0);
        }
        __syncthreads();

        const uint32_t sb = sbase + (kb & 1) * ASTAGE;
        const uint32_t uK = sb, uV = sb + AT;

        // ---- S = Q K^T (2-term, term-major) ----
        float sc[8][4] = {};
        #pragma unroll
        for (int kc = 0; kc < 4; kc++) {
            uint32_t b[4][4];
            #pragma unroll
            for (int j = 0; j < 4; j++) {
                int bbyte = (j * 16 + ((lane >> 4) << 3) + (lane & 7)) * (AP * 2)
                          + kc * 32 + ((lane >> 3) & 1) * 16;
                ldmx4(b[j], uK + bbyte);
            }
            #pragma unroll
            for (int j = 0; j < 4; j++) {
                mma16816h(sc[2 * j],     aq_h[kc], b[j][0], b[j][1]);
                mma16816h(sc[2 * j + 1], aq_h[kc], b[j][2], b[j][3]);
            }
            #pragma unroll
            for (int j = 0; j < 4; j++) {
                mma16816h(sc[2 * j],     aq_l[kc], b[j][0], b[j][1]);
                mma16816h(sc[2 * j + 1], aq_l[kc], b[j][2], b[j][3]);
            }
        }

        // ---- causal mask ----
        if (kb == qb) {
            int r0l = wid * 16 + (lane >> 2);
            #pragma unroll
            for (int nt = 0; nt < 8; nt++) {
                int col = nt * 8 + (lane & 3) * 2;
                if (col > r0l)         sc[nt][0] = -1e30f;
                if (col + 1 > r0l)     sc[nt][1] = -1e30f;
                if (col > r0l + 8)     sc[nt][2] = -1e30f;
                if (col + 1 > r0l + 8) sc[nt][3] = -1e30f;
            }
        }

        // ---- online softmax (base-2) ----
        float mx0 = -1e30f, mx1 = -1e30f;
        #pragma unroll
        for (int nt = 0; nt < 8; nt++) {
            mx0 = fmaxf(mx0, fmaxf(sc[nt][0], sc[nt][1]));
            mx1 = fmaxf(mx1, fmaxf(sc[nt][2], sc[nt][3]));
        }
        mx0 = fmaxf(mx0, __shfl_xor_sync(0xffffffffu, mx0, 1));
        mx0 = fmaxf(mx0, __shfl_xor_sync(0xffffffffu, mx0, 2));
        mx1 = fmaxf(mx1, __shfl_xor_sync(0xffffffffu, mx1, 1));
        mx1 = fmaxf(mx1, __shfl_xor_sync(0xffffffffu, mx1, 2));

        float mn0 = fmaxf(m0r, mx0), mn1 = fmaxf(m1r, mx1);
        float cr0 = ex2(m0r - mn0), cr1 = ex2(m1r - mn1);

        float sum0 = 0.0f, sum1 = 0.0f;
        #pragma unroll
        for (int nt = 0; nt < 8; nt++) {
            float p0 = ex2(sc[nt][0] - mn0);
            float p1 = ex2(sc[nt][1] - mn0);
            float p2 = ex2(sc[nt][2] - mn1);
            float p3 = ex2(sc[nt][3] - mn1);
            sc[nt][0] = p0; sc[nt][1] = p1; sc[nt][2] = p2; sc[nt][3] = p3;
            sum0 += p0 + p1;
            sum1 += p2 + p3;
        }
        sum0 += __shfl_xor_sync(0xffffffffu, sum0, 1);
        sum0 += __shfl_xor_sync(0xffffffffu, sum0, 2);
        sum1 += __shfl_xor_sync(0xffffffffu, sum1, 1);
        sum1 += __shfl_xor_sync(0xffffffffu, sum1, 2);

        l0 = l0 * cr0 + sum0;  m0r = mn0;
        l1 = l1 * cr1 + sum1;  m1r = mn1;

        #pragma unroll
        for (int nt = 0; nt < 8; nt++) {
            oAcc[nt][0] *= cr0; oAcc[nt][1] *= cr0;
            oAcc[nt][2] *= cr1; oAcc[nt][3] *= cr1;
        }

        // ---- O += P V (2-term: P hi/lo, V single; term-major) ----
        #pragma unroll
        for (int kc = 0; kc < 4; kc++) {
            uint32_t pa_h[4], pa_l[4];
            pack_pair_h(sc[2 * kc][0],     sc[2 * kc][1],     pa_h[0], pa_l[0]);
            pack_pair_h(sc[2 * kc][2],     sc[2 * kc][3],     pa_h[1], pa_l[1]);
            pack_pair_h(sc[2 * kc + 1][0], sc[2 * kc + 1][1], pa_h[2], pa_l[2]);
            pack_pair_h(sc[2 * kc + 1][2], sc[2 * kc + 1][3], pa_h[3], pa_l[3]);
            uint32_t v[4][4];
            #pragma unroll
            for (int j = 0; j < 4; j++) {
                int key   = kc * 16 + ((lane >> 3) & 1) * 8 + (lane & 7);
                int hd    = j * 16 + (lane >> 4) * 8;
                int vbyte = key * (AP * 2) + hd * 2;
                ldmx4t(v[j], uV + vbyte);
            }
            #pragma unroll
            for (int j = 0; j < 4; j++) {
                mma16816h(oAcc[2 * j],     pa_h, v[j][0], v[j][1]);
                mma16816h(oAcc[2 * j + 1], pa_h, v[j][2], v[j][3]);
            }
            #pragma unroll
            for (int j = 0; j < 4; j++) {
                mma16816h(oAcc[2 * j],     pa_l, v[j][0], v[j][1]);
                mma16816h(oAcc[2 * j + 1], pa_l, v[j][2], v[j][3]);
            }
        }
        __syncthreads();
    }

    // ---- finalize: ctx single fp16 [B,S,D] ----
    const float inv0 = 1.0f / l0, inv1 = 1.0f / l1;
    const int b = bh >> 4, h = bh & 15;
    const int r0 = qb * 64 + wid * 16 + (lane >> 2);
    const int r1 = r0 + 8;
    #pragma unroll
    for (int nt = 0; nt < 8; nt++) {
        int hd = nt * 8 + (lane & 3) * 2;
        float v0 = oAcc[nt][0] * inv0, v1 = oAcc[nt][1] * inv0;
        float v2 = oAcc[nt][2] * inv1, v3 = oAcc[nt][3] * inv1;
        size_t o0 = ((size_t)(b * S_ + r0)) * D_ + h * HD_ + hd;
        size_t o1 = ((size_t)(b * S_ + r1)) * D_ + h * HD_ + hd;
        *(unsigned*)&g_ctx[o0] = pack_h2(v0, v1);
        *(unsigned*)&g_ctx[o1] = pack_h2(v2, v3);
    }
}

// ---------------------------------------------------------------------------
// fp32 -> (fp16 hi, fp16 lo) split of x
// ---------------------------------------------------------------------------
__global__ void split_x_kernel(const float4* __restrict__ src)
{
    int i = blockIdx.x * blockDim.x + threadIdx.x;
    if (i >= GM * GK / 4) return;
    float4 v = src[i];
    unsigned h0, l0p, h1, l1p;
    pack_pair_h(v.x, v.y, h0, l0p);
    pack_pair_h(v.z, v.w, h1, l1p);
    ((unsigned*)g_x_hi)[i * 2]     = h0;
    ((unsigned*)g_x_hi)[i * 2 + 1] = h1;
    ((unsigned*)g_x_lo)[i * 2]     = l0p;
    ((unsigned*)g_x_lo)[i * 2 + 1] = l1p;
}

// ---------------------------------------------------------------------------
// Batched: W [K,N] fp32 -> Wt [N,K] single fp16 for all 4 weights (blockIdx.z)
// ---------------------------------------------------------------------------
__global__ void transpose_split4_kernel(const float* __restrict__ W0,
                                        const float* __restrict__ W1,
                                        const float* __restrict__ W2,
                                        const float* __restrict__ W3)
{
    __shared__ float tile[32][33];
    const float* W;
    __half* dst;
    switch (blockIdx.z) {
        case 0:  W = W0; dst = g_wqt; break;
        case 1:  W = W1; dst = g_wkt; break;
        case 2:  W = W2; dst = g_wvt; break;
        default: W = W3; dst = g_wot; break;
    }
    const int tx = threadIdx.x, ty = threadIdx.y;
    const int k0 = blockIdx.y * 32;
    const int n0 = blockIdx.x * 32;
    #pragma unroll
    for (int j = 0; j < 4; j++)
        tile[ty + j * 8][tx] = W[(size_t)(k0 + ty + j * 8) * GN + n0 + tx];
    __syncthreads();
    #pragma unroll
    for (int j = 0; j < 4; j++) {
        int n = n0 + ty + j * 8;
        int k = k0 + tx;
        dst[(size_t)n * GK + k] = __float2half_rn(tile[tx][ty + j * 8]);
    }
}

// ---------------------------------------------------------------------------
extern "C" void kernel_launch(void* const* d_in, const int* in_sizes, int n_in,
                              void* d_out, int out_size)
{
    const float* x  = (const float*)d_in[0];
    const float* Wq = (const float*)d_in[1];
    const float* Wk = (const float*)d_in[2];
    const float* Wv = (const float*)d_in[3];
    const float* Wo = (const float*)d_in[4];
    const float* bo = (const float*)d_in[5];
    float*       out = (float*)d_out;

    cudaFuncSetAttribute(mma_gemm_kernel<0>,
                         cudaFuncAttributeMaxDynamicSharedMemorySize, 3 * 3 * GT);
    cudaFuncSetAttribute(mma_gemm_kernel<1>,
                         cudaFuncAttributeMaxDynamicSharedMemorySize, 3 * 2 * GT);
    cudaFuncSetAttribute(mma_gemm_kernel<2>,
                         cudaFuncAttributeMaxDynamicSharedMemorySize, 3 * 2 * GT);
    cudaFuncSetAttribute(attn_mma_kernel,
                         cudaFuncAttributeMaxDynamicSharedMemorySize, SMEM_ATTN);

    // 1) prep: split x (fp16 hi/lo), transpose weights to single fp16
    split_x_kernel<<<(GM * GK / 4 + 255) / 256, 256>>>((const float4*)x);
    transpose_split4_kernel<<<dim3(GN / 32, GK / 32, 4), dim3(32, 8)>>>(Wq, Wk, Wv, Wo);

    // 2) Q projection (2-term, 3-stage) -> fp16 hi/lo, pre-scaled
    mma_gemm_kernel<0><<<dim3(GN / 128, GM / 128, 1), 256, 3 * 3 * GT>>>(nullptr, nullptr);
    // 2b) K/V projections (1-term, 3-stage) -> fp16 single
    mma_gemm_kernel<1><<<dim3(GN / 128, GM / 128, 2), 256, 3 * 2 * GT>>>(nullptr, nullptr);

    // 3) attention (2-term fp16) -> ctx single fp16
    attn_mma_kernel<<<dim3(S_ / 64, B_ * H_), 128, SMEM_ATTN>>>();

    // 4) output projection (1-term, 3-stage) + bias -> fp32 out
    mma_gemm_kernel<2><<<dim3(GN / 128, GM / 128, 1), 256, 3 * 2 * GT>>>(bo, out);
}